// round 1
// baseline (speedup 1.0000x reference)
#include <cuda_runtime.h>
#include <math.h>

#define BB     64
#define LATENT 128
#define EMBD   512
#define HID    1024
#define VOC    32000
#define TSTEPS 64
#define NG     4096
#define NLBLK  125   // logits blocks (125 * 256 cols = 32000)

// ---------------- recurrent state (device globals; no allocation) ----------
__device__ float g_h[BB * HID];
__device__ float g_c[BB * HID];
__device__ int   g_tok[BB];
__device__ float g_gpart[4 * BB * NG];      // K-split partial gate sums
__device__ float g_pval[BB * NLBLK];        // per-block argmax partials
__device__ int   g_pidx[BB * NLBLK];

typedef unsigned long long u64;

// ---- packed fp32x2 FMA (Blackwell FFMA2; ptxas won't emit from C++) -------
__device__ __forceinline__ u64 pk2(float x, float y) {
    u64 r; asm("mov.b64 %0, {%1,%2};" : "=l"(r) : "f"(x), "f"(y)); return r;
}
__device__ __forceinline__ void fma2(u64& d, u64 a, u64 b) {
    asm("fma.rn.f32x2 %0, %1, %2, %0;" : "+l"(d) : "l"(a), "l"(b));
}
__device__ __forceinline__ float2 upk2(u64 v) {
    float lo, hi; asm("mov.b64 {%0,%1}, %2;" : "=f"(lo), "=f"(hi) : "l"(v));
    return make_float2(lo, hi);
}

// ---------------- init: h = z @ lth_w^T + lth_b ; c = 0 ; tok = 0 ----------
__global__ void k_init(const float* __restrict__ z,
                       const float* __restrict__ lw,
                       const float* __restrict__ lb) {
    int idx = blockIdx.x * 256 + threadIdx.x;      // 65536 = BB*HID
    int r = idx >> 10;
    int u = idx & (HID - 1);
    float s = lb[u];
    const float* zr = z + r * LATENT;
    const float* wr = lw + (size_t)u * LATENT;
    #pragma unroll 8
    for (int k = 0; k < LATENT; k++) s += zr[k] * wr[k];
    g_h[idx] = s;
    g_c[idx] = 0.f;
    if (idx < BB) g_tok[idx] = 0;
}

// ---------------- gates partial GEMM --------------------------------------
// grid (32, 4): blockIdx.x = 128-col tile of the 4096 gate cols,
//               blockIdx.y = K-split (384 of the virtual K = 512(emb)+1024(h))
// tile 64x128, 256 threads, thread tile 8 rows x 4 cols (2 f32x2 pairs)
__global__ void __launch_bounds__(256, 1)
k_gates(const float* __restrict__ emb,
        const float* __restrict__ wih,
        const float* __restrict__ whh) {
    __shared__ float As[32][68];    // [k][row], padded
    __shared__ float Bs[32][132];   // [k][col], padded
    __shared__ int   stok[BB];

    const int tid = threadIdx.x;
    const int cb  = blockIdx.x;
    const int ks  = blockIdx.y;
    if (tid < BB) stok[tid] = g_tok[tid];
    __syncthreads();

    const int tx = tid & 31, ty = tid >> 5;
    u64 acc[8][2];
    #pragma unroll
    for (int i = 0; i < 8; i++) { acc[i][0] = pk2(0.f, 0.f); acc[i][1] = pk2(0.f, 0.f); }

    const int c0 = cb * 128;
    for (int ch = 0; ch < 12; ch++) {
        const int kb = ks * 384 + ch * 32;   // virtual k base (chunks never straddle 512)
        // A: 64 rows x 32 k
        #pragma unroll
        for (int i = 0; i < 2; i++) {
            int l = tid * 2 + i;                 // 0..511
            int row = l >> 3, kq = l & 7;
            float4 v;
            if (kb < 512) v = *(const float4*)&emb[(size_t)stok[row] * EMBD + kb + kq * 4];
            else          v = *(const float4*)&g_h[row * HID + (kb - 512) + kq * 4];
            As[kq * 4 + 0][row] = v.x; As[kq * 4 + 1][row] = v.y;
            As[kq * 4 + 2][row] = v.z; As[kq * 4 + 3][row] = v.w;
        }
        // B: 128 cols x 32 k  (weights are [out][in] row-major)
        #pragma unroll
        for (int i = 0; i < 4; i++) {
            int l = tid * 4 + i;                 // 0..1023
            int c = l >> 3, kq = l & 7;
            float4 v;
            if (kb < 512) v = *(const float4*)&wih[(size_t)(c0 + c) * EMBD + kb + kq * 4];
            else          v = *(const float4*)&whh[(size_t)(c0 + c) * HID + (kb - 512) + kq * 4];
            Bs[kq * 4 + 0][c] = v.x; Bs[kq * 4 + 1][c] = v.y;
            Bs[kq * 4 + 2][c] = v.z; Bs[kq * 4 + 3][c] = v.w;
        }
        __syncthreads();
        #pragma unroll 4
        for (int k = 0; k < 32; k++) {
            float4 a0 = *(const float4*)&As[k][ty * 8];
            float4 a1 = *(const float4*)&As[k][ty * 8 + 4];
            float4 b  = *(const float4*)&Bs[k][tx * 4];
            u64 p0 = pk2(b.x, b.y), p1 = pk2(b.z, b.w);
            float ar[8] = {a0.x, a0.y, a0.z, a0.w, a1.x, a1.y, a1.z, a1.w};
            #pragma unroll
            for (int r = 0; r < 8; r++) {
                u64 aa = pk2(ar[r], ar[r]);
                fma2(acc[r][0], aa, p0);
                fma2(acc[r][1], aa, p1);
            }
        }
        __syncthreads();
    }
    float* dst = g_gpart + (size_t)ks * BB * NG;
    #pragma unroll
    for (int r = 0; r < 8; r++) {
        int row = ty * 8 + r;
        float2 v0 = upk2(acc[r][0]), v1 = upk2(acc[r][1]);
        float4 o = make_float4(v0.x, v0.y, v1.x, v1.y);
        *(float4*)&dst[(size_t)row * NG + c0 + tx * 4] = o;
    }
}

// ---------------- LSTM pointwise: reduce K-splits, activations -------------
__global__ void k_lstm(const float* __restrict__ bih,
                       const float* __restrict__ bhh) {
    int idx = blockIdx.x * 256 + threadIdx.x;   // 65536 = BB*HID
    int r = idx >> 10;
    int u = idx & (HID - 1);
    float gv[4];
    #pragma unroll
    for (int g = 0; g < 4; g++) {
        int col = g * HID + u;
        float s = bih[col] + bhh[col];
        const float* p = g_gpart + (size_t)r * NG + col;
        #pragma unroll
        for (int ks = 0; ks < 4; ks++) s += p[(size_t)ks * BB * NG];
        gv[g] = s;
    }
    float ig = 1.f / (1.f + expf(-gv[0]));
    float fg = 1.f / (1.f + expf(-gv[1]));
    float gg = tanhf(gv[2]);
    float og = 1.f / (1.f + expf(-gv[3]));
    float c2 = fg * g_c[idx] + ig * gg;
    float h2 = og * tanhf(c2);
    g_c[idx] = c2;
    g_h[idx] = h2;
}

// ---------------- logits GEMM + fused per-block argmax ---------------------
// 125 blocks x 256 vocab cols; tile 64x256, thread tile 8x8 (4 f32x2 pairs)
__global__ void __launch_bounds__(256, 1)
k_logits(const float* __restrict__ fcw,
         const float* __restrict__ fcb,
         float* __restrict__ out, int t) {
    __shared__ float As[32][68];    // [k][row]
    __shared__ float Bs[32][264];   // [k][vcol]
    const int tid = threadIdx.x;
    const int tx = tid & 31, ty = tid >> 5;
    const int v0 = blockIdx.x * 256;

    u64 acc[8][4];
    #pragma unroll
    for (int i = 0; i < 8; i++)
        #pragma unroll
        for (int j = 0; j < 4; j++) acc[i][j] = pk2(0.f, 0.f);

    for (int ch = 0; ch < 32; ch++) {
        const int kb = ch * 32;
        #pragma unroll
        for (int i = 0; i < 2; i++) {
            int l = tid * 2 + i;                 // 0..511
            int row = l >> 3, kq = l & 7;
            float4 v = *(const float4*)&g_h[row * HID + kb + kq * 4];
            As[kq * 4 + 0][row] = v.x; As[kq * 4 + 1][row] = v.y;
            As[kq * 4 + 2][row] = v.z; As[kq * 4 + 3][row] = v.w;
        }
        #pragma unroll
        for (int i = 0; i < 8; i++) {
            int l = tid * 8 + i;                 // 0..2047
            int c = l >> 3, kq = l & 7;          // c == tid : 128B contiguous per thread
            float4 v = *(const float4*)&fcw[(size_t)(v0 + c) * HID + kb + kq * 4];
            Bs[kq * 4 + 0][c] = v.x; Bs[kq * 4 + 1][c] = v.y;
            Bs[kq * 4 + 2][c] = v.z; Bs[kq * 4 + 3][c] = v.w;
        }
        __syncthreads();
        #pragma unroll 4
        for (int k = 0; k < 32; k++) {
            float4 a0 = *(const float4*)&As[k][ty * 8];
            float4 a1 = *(const float4*)&As[k][ty * 8 + 4];
            float4 b0 = *(const float4*)&Bs[k][tx * 8];
            float4 b1 = *(const float4*)&Bs[k][tx * 8 + 4];
            u64 p0 = pk2(b0.x, b0.y), p1 = pk2(b0.z, b0.w);
            u64 p2 = pk2(b1.x, b1.y), p3 = pk2(b1.z, b1.w);
            float ar[8] = {a0.x, a0.y, a0.z, a0.w, a1.x, a1.y, a1.z, a1.w};
            #pragma unroll
            for (int r = 0; r < 8; r++) {
                u64 aa = pk2(ar[r], ar[r]);
                fma2(acc[r][0], aa, p0);
                fma2(acc[r][1], aa, p1);
                fma2(acc[r][2], aa, p2);
                fma2(acc[r][3], aa, p3);
            }
        }
        __syncthreads();
    }

    float4 cb0 = *(const float4*)&fcb[v0 + tx * 8];
    float4 cb1 = *(const float4*)&fcb[v0 + tx * 8 + 4];
    const int vbase = v0 + tx * 8;
    #pragma unroll
    for (int r = 0; r < 8; r++) {
        int row = ty * 8 + r;
        float2 q0 = upk2(acc[r][0]), q1 = upk2(acc[r][1]);
        float2 q2 = upk2(acc[r][2]), q3 = upk2(acc[r][3]);
        float vals[8] = {q0.x + cb0.x, q0.y + cb0.y, q1.x + cb0.z, q1.y + cb0.w,
                         q2.x + cb1.x, q2.y + cb1.y, q3.x + cb1.z, q3.y + cb1.w};
        float* op = out + (size_t)row * TSTEPS * VOC + (size_t)t * VOC + vbase;
        *(float4*)op       = make_float4(vals[0], vals[1], vals[2], vals[3]);
        *(float4*)(op + 4) = make_float4(vals[4], vals[5], vals[6], vals[7]);
        // local argmax (first-index tie break like jnp.argmax)
        float mv = vals[0]; int mi = vbase;
        #pragma unroll
        for (int j = 1; j < 8; j++)
            if (vals[j] > mv) { mv = vals[j]; mi = vbase + j; }
        #pragma unroll
        for (int off = 16; off > 0; off >>= 1) {
            float ov = __shfl_xor_sync(0xffffffffu, mv, off);
            int   oi = __shfl_xor_sync(0xffffffffu, mi, off);
            if (ov > mv || (ov == mv && oi < mi)) { mv = ov; mi = oi; }
        }
        if (tx == 0) {
            g_pval[row * NLBLK + blockIdx.x] = mv;
            g_pidx[row * NLBLK + blockIdx.x] = mi;
        }
    }
}

// ---------------- final argmax reduce --------------------------------------
__global__ void k_argmax() {
    int r = threadIdx.x;                        // 64 threads
    float bv = -3.4e38f; int bi = 0;
    for (int b = 0; b < NLBLK; b++) {
        float v = g_pval[r * NLBLK + b];
        int   i = g_pidx[r * NLBLK + b];
        if (v > bv || (v == bv && i < bi)) { bv = v; bi = i; }
    }
    g_tok[r] = bi;
}

// ---------------- launch ----------------------------------------------------
extern "C" void kernel_launch(void* const* d_in, const int* in_sizes, int n_in,
                              void* d_out, int out_size) {
    const float* z   = (const float*)d_in[0];
    const float* emb = (const float*)d_in[1];
    const float* wih = (const float*)d_in[2];
    const float* whh = (const float*)d_in[3];
    const float* bih = (const float*)d_in[4];
    const float* bhh = (const float*)d_in[5];
    const float* fcw = (const float*)d_in[6];
    const float* fcb = (const float*)d_in[7];
    const float* lw  = (const float*)d_in[8];
    const float* lb  = (const float*)d_in[9];
    float* out = (float*)d_out;

    k_init<<<256, 256>>>(z, lw, lb);
    for (int t = 0; t < TSTEPS; t++) {
        k_gates<<<dim3(32, 4), 256>>>(emb, wih, whh);
        k_lstm<<<256, 256>>>(bih, bhh);
        k_logits<<<NLBLK, 256>>>(fcw, fcb, out, t);
        if (t < TSTEPS - 1) k_argmax<<<1, 64>>>();
    }
}

// round 2
// speedup vs baseline: 1.0242x; 1.0242x over previous
#include <cuda_runtime.h>
#include <math.h>

#define BB     64
#define LATENT 128
#define EMBD   512
#define HID    1024
#define VOC    32000
#define TSTEPS 64
#define NG     4096
#define NLBLK  125    // logits blocks
#define NPART  250    // argmax partials per row (2 per block)
#define KC     16     // logits k-chunk

// ---------------- recurrent state (device globals; no allocation) ----------
__device__ float g_h[BB * HID];
__device__ float g_c[BB * HID];
__device__ int   g_tok[BB];
__device__ float g_gpart[4 * BB * NG];
__device__ float g_pval[BB * NPART];
__device__ int   g_pidx[BB * NPART];

typedef unsigned long long u64;

__device__ __forceinline__ u64 pk2(float x, float y) {
    u64 r; asm("mov.b64 %0, {%1,%2};" : "=l"(r) : "f"(x), "f"(y)); return r;
}
__device__ __forceinline__ void fma2(u64& d, u64 a, u64 b) {
    asm("fma.rn.f32x2 %0, %1, %2, %0;" : "+l"(d) : "l"(a), "l"(b));
}
__device__ __forceinline__ float2 upk2(u64 v) {
    float lo, hi; asm("mov.b64 {%0,%1}, %2;" : "=f"(lo), "=f"(hi) : "l"(v));
    return make_float2(lo, hi);
}

// ---------------- init: h = z @ lth_w^T + lth_b ; c = 0 ; tok = 0 ----------
__global__ void k_init(const float* __restrict__ z,
                       const float* __restrict__ lw,
                       const float* __restrict__ lb) {
    int idx = blockIdx.x * 256 + threadIdx.x;
    int r = idx >> 10;
    int u = idx & (HID - 1);
    float s = lb[u];
    const float* zr = z + r * LATENT;
    const float* wr = lw + (size_t)u * LATENT;
    #pragma unroll 8
    for (int k = 0; k < LATENT; k++) s += zr[k] * wr[k];
    g_h[idx] = s;
    g_c[idx] = 0.f;
    if (idx < BB) g_tok[idx] = 0;
}

// ---------------- gates partial GEMM (unchanged this round) ----------------
__global__ void __launch_bounds__(256, 1)
k_gates(const float* __restrict__ emb,
        const float* __restrict__ wih,
        const float* __restrict__ whh) {
    __shared__ float As[32][68];
    __shared__ float Bs[32][132];
    __shared__ int   stok[BB];

    const int tid = threadIdx.x;
    const int cb  = blockIdx.x;
    const int ks  = blockIdx.y;
    if (tid < BB) stok[tid] = g_tok[tid];
    __syncthreads();

    const int tx = tid & 31, ty = tid >> 5;
    u64 acc[8][2];
    #pragma unroll
    for (int i = 0; i < 8; i++) { acc[i][0] = pk2(0.f, 0.f); acc[i][1] = pk2(0.f, 0.f); }

    const int c0 = cb * 128;
    for (int ch = 0; ch < 12; ch++) {
        const int kb = ks * 384 + ch * 32;
        #pragma unroll
        for (int i = 0; i < 2; i++) {
            int l = tid * 2 + i;
            int row = l >> 3, kq = l & 7;
            float4 v;
            if (kb < 512) v = *(const float4*)&emb[(size_t)stok[row] * EMBD + kb + kq * 4];
            else          v = *(const float4*)&g_h[row * HID + (kb - 512) + kq * 4];
            As[kq * 4 + 0][row] = v.x; As[kq * 4 + 1][row] = v.y;
            As[kq * 4 + 2][row] = v.z; As[kq * 4 + 3][row] = v.w;
        }
        #pragma unroll
        for (int i = 0; i < 4; i++) {
            int l = tid * 4 + i;
            int c = l >> 3, kq = l & 7;
            float4 v;
            if (kb < 512) v = *(const float4*)&wih[(size_t)(c0 + c) * EMBD + kb + kq * 4];
            else          v = *(const float4*)&whh[(size_t)(c0 + c) * HID + (kb - 512) + kq * 4];
            Bs[kq * 4 + 0][c] = v.x; Bs[kq * 4 + 1][c] = v.y;
            Bs[kq * 4 + 2][c] = v.z; Bs[kq * 4 + 3][c] = v.w;
        }
        __syncthreads();
        #pragma unroll 4
        for (int k = 0; k < 32; k++) {
            float4 a0 = *(const float4*)&As[k][ty * 8];
            float4 a1 = *(const float4*)&As[k][ty * 8 + 4];
            float4 b  = *(const float4*)&Bs[k][tx * 4];
            u64 p0 = pk2(b.x, b.y), p1 = pk2(b.z, b.w);
            float ar[8] = {a0.x, a0.y, a0.z, a0.w, a1.x, a1.y, a1.z, a1.w};
            #pragma unroll
            for (int r = 0; r < 8; r++) {
                u64 aa = pk2(ar[r], ar[r]);
                fma2(acc[r][0], aa, p0);
                fma2(acc[r][1], aa, p1);
            }
        }
        __syncthreads();
    }
    float* dst = g_gpart + (size_t)ks * BB * NG;
    #pragma unroll
    for (int r = 0; r < 8; r++) {
        int row = ty * 8 + r;
        float2 v0 = upk2(acc[r][0]), v1 = upk2(acc[r][1]);
        float4 o = make_float4(v0.x, v0.y, v1.x, v1.y);
        *(float4*)&dst[(size_t)row * NG + c0 + tx * 4] = o;
    }
}

// ---------------- LSTM pointwise (unchanged) -------------------------------
__global__ void k_lstm(const float* __restrict__ bih,
                       const float* __restrict__ bhh) {
    int idx = blockIdx.x * 256 + threadIdx.x;
    int r = idx >> 10;
    int u = idx & (HID - 1);
    float gv[4];
    #pragma unroll
    for (int g = 0; g < 4; g++) {
        int col = g * HID + u;
        float s = bih[col] + bhh[col];
        const float* p = g_gpart + (size_t)r * NG + col;
        #pragma unroll
        for (int ks = 0; ks < 4; ks++) s += p[(size_t)ks * BB * NG];
        gv[g] = s;
    }
    float ig = 1.f / (1.f + expf(-gv[0]));
    float fg = 1.f / (1.f + expf(-gv[1]));
    float gg = tanhf(gv[2]);
    float og = 1.f / (1.f + expf(-gv[3]));
    float c2 = fg * g_c[idx] + ig * gg;
    float h2 = og * tanhf(c2);
    g_c[idx] = c2;
    g_h[idx] = h2;
}

// ---------------- logits GEMM: 512 thr, pipelined, dup-A smem --------------
// 125 blocks x 256 vocab cols; tile 64x256, thread tile 8 rows x 4 cols.
// As holds rows pre-duplicated: As[k][2r]=As[k][2r+1]=a(r)  ->  ld.v2.u64
// yields ready (a,a) packed pairs, zero MOV overhead before FFMA2.
__global__ void __launch_bounds__(512, 1)
k_logits(const float* __restrict__ fcw,
         const float* __restrict__ fcb,
         float* __restrict__ out, int t) {
    __shared__ float As[2][KC][128];   // duplicated rows (64 rows -> 128 slots)
    __shared__ float Bs[2][KC][256];

    const int tid = threadIdx.x;
    const int cg  = tid & 63;          // cols cg*4 .. cg*4+3
    const int rg  = tid >> 6;          // rows rg*8 .. rg*8+7
    const int v0  = blockIdx.x * 256;

    // fill roles: tid<256 -> one vocab column's full 64B k-chunk (coalesced
    // full sectors); tid>=256 -> A (g_h) float4
    const int bcol = tid;
    const int arow = (tid - 256) >> 2;
    const int akq  = (tid - 256) & 3;

    float4 bst0, bst1, bst2, bst3, ast;

    auto ldg_chunk = [&](int ch) {
        int kb = ch * KC;
        if (tid < 256) {
            const float4* p = (const float4*)(fcw + (size_t)(v0 + bcol) * HID + kb);
            bst0 = p[0]; bst1 = p[1]; bst2 = p[2]; bst3 = p[3];
        } else {
            ast = *(const float4*)&g_h[arow * HID + kb + akq * 4];
        }
    };
    auto sts_chunk = [&](int buf) {
        if (tid < 256) {
            Bs[buf][ 0][bcol] = bst0.x; Bs[buf][ 1][bcol] = bst0.y;
            Bs[buf][ 2][bcol] = bst0.z; Bs[buf][ 3][bcol] = bst0.w;
            Bs[buf][ 4][bcol] = bst1.x; Bs[buf][ 5][bcol] = bst1.y;
            Bs[buf][ 6][bcol] = bst1.z; Bs[buf][ 7][bcol] = bst1.w;
            Bs[buf][ 8][bcol] = bst2.x; Bs[buf][ 9][bcol] = bst2.y;
            Bs[buf][10][bcol] = bst2.z; Bs[buf][11][bcol] = bst2.w;
            Bs[buf][12][bcol] = bst3.x; Bs[buf][13][bcol] = bst3.y;
            Bs[buf][14][bcol] = bst3.z; Bs[buf][15][bcol] = bst3.w;
        } else {
            int k0 = akq * 4, d = 2 * arow;
            *(float2*)&As[buf][k0 + 0][d] = make_float2(ast.x, ast.x);
            *(float2*)&As[buf][k0 + 1][d] = make_float2(ast.y, ast.y);
            *(float2*)&As[buf][k0 + 2][d] = make_float2(ast.z, ast.z);
            *(float2*)&As[buf][k0 + 3][d] = make_float2(ast.w, ast.w);
        }
    };

    u64 acc[8][2];
    #pragma unroll
    for (int r = 0; r < 8; r++) { acc[r][0] = pk2(0.f, 0.f); acc[r][1] = pk2(0.f, 0.f); }

    // prologue
    ldg_chunk(0);
    sts_chunk(0);
    __syncthreads();

    for (int ch = 0; ch < HID / KC; ch++) {
        const int buf = ch & 1;
        if (ch + 1 < HID / KC) ldg_chunk(ch + 1);   // LDGs fly during compute
        #pragma unroll
        for (int k = 0; k < KC; k++) {
            ulonglong2 b2 = *(const ulonglong2*)&Bs[buf][k][cg * 4];
            ulonglong2 a0 = *(const ulonglong2*)&As[buf][k][rg * 16];
            ulonglong2 a1 = *(const ulonglong2*)&As[buf][k][rg * 16 + 4];
            ulonglong2 a2 = *(const ulonglong2*)&As[buf][k][rg * 16 + 8];
            ulonglong2 a3 = *(const ulonglong2*)&As[buf][k][rg * 16 + 12];
            fma2(acc[0][0], a0.x, b2.x); fma2(acc[0][1], a0.x, b2.y);
            fma2(acc[1][0], a0.y, b2.x); fma2(acc[1][1], a0.y, b2.y);
            fma2(acc[2][0], a1.x, b2.x); fma2(acc[2][1], a1.x, b2.y);
            fma2(acc[3][0], a1.y, b2.x); fma2(acc[3][1], a1.y, b2.y);
            fma2(acc[4][0], a2.x, b2.x); fma2(acc[4][1], a2.x, b2.y);
            fma2(acc[5][0], a2.y, b2.x); fma2(acc[5][1], a2.y, b2.y);
            fma2(acc[6][0], a3.x, b2.x); fma2(acc[6][1], a3.x, b2.y);
            fma2(acc[7][0], a3.y, b2.x); fma2(acc[7][1], a3.y, b2.y);
        }
        if (ch + 1 < HID / KC) sts_chunk(buf ^ 1);  // target buf free since last sync
        __syncthreads();
    }

    // epilogue: bias, store logits, per-warp argmax (2 partials per block)
    const int vb = v0 + cg * 4;
    float4 cb = *(const float4*)&fcb[vb];
    const int lane = tid & 31;
    const int half = (tid >> 5) & 1;
    #pragma unroll
    for (int r = 0; r < 8; r++) {
        int row = rg * 8 + r;
        float2 q0 = upk2(acc[r][0]), q1 = upk2(acc[r][1]);
        float w0 = q0.x + cb.x, w1 = q0.y + cb.y;
        float w2 = q1.x + cb.z, w3 = q1.y + cb.w;
        *(float4*)&out[(size_t)row * TSTEPS * VOC + (size_t)t * VOC + vb] =
            make_float4(w0, w1, w2, w3);
        float mv = w0; int mi = vb;
        if (w1 > mv) { mv = w1; mi = vb + 1; }
        if (w2 > mv) { mv = w2; mi = vb + 2; }
        if (w3 > mv) { mv = w3; mi = vb + 3; }
        #pragma unroll
        for (int off = 16; off > 0; off >>= 1) {
            float ov = __shfl_xor_sync(0xffffffffu, mv, off);
            int   oi = __shfl_xor_sync(0xffffffffu, mi, off);
            if (ov > mv || (ov == mv && oi < mi)) { mv = ov; mi = oi; }
        }
        if (lane == 0) {
            int slot = row * NPART + blockIdx.x * 2 + half;
            g_pval[slot] = mv;
            g_pidx[slot] = mi;
        }
    }
}

// ---------------- final argmax reduce (4 threads per row) -------------------
__global__ void k_argmax() {
    int tid = threadIdx.x;              // 256
    int r = tid >> 2, q = tid & 3;
    float bv = -3.4e38f; int bi = 0x7fffffff;
    for (int b = q; b < NPART; b += 4) {
        float v = g_pval[r * NPART + b];
        int   i = g_pidx[r * NPART + b];
        if (v > bv || (v == bv && i < bi)) { bv = v; bi = i; }
    }
    #pragma unroll
    for (int off = 1; off <= 2; off <<= 1) {
        float ov = __shfl_xor_sync(0xffffffffu, bv, off);
        int   oi = __shfl_xor_sync(0xffffffffu, bi, off);
        if (ov > bv || (ov == bv && oi < bi)) { bv = ov; bi = oi; }
    }
    if (q == 0) g_tok[r] = bi;
}

// ---------------- launch ----------------------------------------------------
extern "C" void kernel_launch(void* const* d_in, const int* in_sizes, int n_in,
                              void* d_out, int out_size) {
    const float* z   = (const float*)d_in[0];
    const float* emb = (const float*)d_in[1];
    const float* wih = (const float*)d_in[2];
    const float* whh = (const float*)d_in[3];
    const float* bih = (const float*)d_in[4];
    const float* bhh = (const float*)d_in[5];
    const float* fcw = (const float*)d_in[6];
    const float* fcb = (const float*)d_in[7];
    const float* lw  = (const float*)d_in[8];
    const float* lb  = (const float*)d_in[9];
    float* out = (float*)d_out;

    k_init<<<256, 256>>>(z, lw, lb);
    for (int t = 0; t < TSTEPS; t++) {
        k_gates<<<dim3(32, 4), 256>>>(emb, wih, whh);
        k_lstm<<<256, 256>>>(bih, bhh);
        k_logits<<<NLBLK, 512>>>(fcw, fcb, out, t);
        if (t < TSTEPS - 1) k_argmax<<<1, 256>>>();
    }
}

// round 5
// speedup vs baseline: 2.7928x; 2.7269x over previous
#include <cuda_runtime.h>
#include <cuda_fp16.h>
#include <math.h>

#define BB     64
#define LATENT 128
#define EMBD   512
#define HID    1024
#define VOC    32000
#define TSTEPS 64
#define NG     4096
#define NLBLK  125          // logits CTAs (125 * 256 = 32000)
#define NCHUNK 16           // K chunks of 64 halves (128B rows)
#define INV256 0.00390625f

typedef unsigned long long u64;
typedef unsigned int u32;

// ---------------- device state (no allocation) ------------------------------
__device__ float g_h[BB * HID];
__device__ float g_c[BB * HID];
__device__ int   g_tok[BB];
__device__ float g_gpart[4 * BB * NG];
__device__ float g_pval[BB * NLBLK];
__device__ int   g_pidx[BB * NLBLK];
__device__ __align__(16) __half g_hh[BB * HID];            // h hi (fp16)
__device__ __align__(16) __half g_hl[BB * HID];            // (h - hi) * 256
__device__ __align__(16) __half g_whi[(size_t)VOC * HID];  // fc_w hi
__device__ __align__(16) __half g_wlo[(size_t)VOC * HID];  // (fc_w - hi) * 256

// ---------------- helpers ---------------------------------------------------
__device__ __forceinline__ u64 pk2(float x, float y) {
    u64 r; asm("mov.b64 %0, {%1,%2};" : "=l"(r) : "f"(x), "f"(y)); return r;
}
__device__ __forceinline__ void fma2(u64& d, u64 a, u64 b) {
    asm("fma.rn.f32x2 %0, %1, %2, %0;" : "+l"(d) : "l"(a), "l"(b));
}
__device__ __forceinline__ float2 upk2(u64 v) {
    float lo, hi; asm("mov.b64 {%0,%1}, %2;" : "=f"(lo), "=f"(hi) : "l"(v));
    return make_float2(lo, hi);
}
__device__ __forceinline__ u32 smem_u32(const void* p) {
    u32 a; asm("{ .reg .u64 t; cvta.to.shared.u64 t, %1; cvt.u32.u64 %0, t; }"
               : "=r"(a) : "l"(p));
    return a;
}
__device__ __forceinline__ void cpa16(u32 dst, const void* src) {
    asm volatile("cp.async.cg.shared.global [%0], [%1], 16;" :: "r"(dst), "l"(src));
}
#define CPA_COMMIT() asm volatile("cp.async.commit_group;" ::: "memory")
#define CPA_WAIT0()  asm volatile("cp.async.wait_group 0;" ::: "memory")

__device__ __forceinline__ void ldm4(u32* r, u32 addr) {
    asm volatile("ldmatrix.sync.aligned.m8n8.x4.shared.b16 {%0,%1,%2,%3}, [%4];"
        : "=r"(r[0]), "=r"(r[1]), "=r"(r[2]), "=r"(r[3]) : "r"(addr));
}
__device__ __forceinline__ void mma16816(float* d, const u32* a, const u32* b) {
    asm volatile("mma.sync.aligned.m16n8k16.row.col.f32.f16.f16.f32 "
        "{%0,%1,%2,%3}, {%4,%5,%6,%7}, {%8,%9}, {%0,%1,%2,%3};"
        : "+f"(d[0]), "+f"(d[1]), "+f"(d[2]), "+f"(d[3])
        : "r"(a[0]), "r"(a[1]), "r"(a[2]), "r"(a[3]), "r"(b[0]), "r"(b[1]));
}

#define SWZ(o) ((o) ^ (((o) >> 3) & 0x70))

// SMEM: header 5120B (bias 1024 | spv 2048 | spi 2048), then 2 tile buffers.
// Per buffer: Ahi 8K | Alo 8K | Bhi 32K | Blo 32K
#define AHI_OFF  0
#define ALO_OFF  8192
#define BHI_OFF  16384
#define BLO_OFF  49152
#define BUFSTR   81920
#define HDR      5120
#define DSMEM    (1024 + HDR + 2 * BUFSTR)

// ---------------- init: h = z @ lth_w^T + lth_b -----------------------------
__global__ void k_init(const float* __restrict__ z,
                       const float* __restrict__ lw,
                       const float* __restrict__ lb) {
    int idx = blockIdx.x * 256 + threadIdx.x;
    int r = idx >> 10;
    int u = idx & (HID - 1);
    float s = lb[u];
    const float* zr = z + r * LATENT;
    const float* wr = lw + (size_t)u * LATENT;
    #pragma unroll 8
    for (int k = 0; k < LATENT; k++) s += zr[k] * wr[k];
    g_h[idx] = s;
    g_c[idx] = 0.f;
    __half hh = __float2half_rn(s);
    g_hh[idx] = hh;
    g_hl[idx] = __float2half_rn((s - __half2float(hh)) * 256.0f);
    if (idx < BB) g_tok[idx] = 0;
}

// ---------------- once per launch: split fc_w into fp16 hi/lo ---------------
__global__ void k_prep(const float* __restrict__ fcw) {
    size_t i4 = ((size_t)blockIdx.x * 256 + threadIdx.x) * 4;
    float4 w = *(const float4*)&fcw[i4];
    __half h0 = __float2half_rn(w.x), h1 = __float2half_rn(w.y);
    __half h2 = __float2half_rn(w.z), h3 = __float2half_rn(w.w);
    *(__half2*)&g_whi[i4]     = __halves2half2(h0, h1);
    *(__half2*)&g_whi[i4 + 2] = __halves2half2(h2, h3);
    __half l0 = __float2half_rn((w.x - __half2float(h0)) * 256.f);
    __half l1 = __float2half_rn((w.y - __half2float(h1)) * 256.f);
    __half l2 = __float2half_rn((w.z - __half2float(h2)) * 256.f);
    __half l3 = __float2half_rn((w.w - __half2float(h3)) * 256.f);
    *(__half2*)&g_wlo[i4]     = __halves2half2(l0, l1);
    *(__half2*)&g_wlo[i4 + 2] = __halves2half2(l2, l3);
}

// ---------------- gates partial GEMM (unchanged) ----------------------------
__global__ void __launch_bounds__(256, 1)
k_gates(const float* __restrict__ emb,
        const float* __restrict__ wih,
        const float* __restrict__ whh) {
    __shared__ float As[32][68];
    __shared__ float Bs[32][132];
    __shared__ int   stok[BB];

    const int tid = threadIdx.x;
    const int cb  = blockIdx.x;
    const int ks  = blockIdx.y;
    if (tid < BB) stok[tid] = g_tok[tid];
    __syncthreads();

    const int tx = tid & 31, ty = tid >> 5;
    u64 acc[8][2];
    #pragma unroll
    for (int i = 0; i < 8; i++) { acc[i][0] = pk2(0.f, 0.f); acc[i][1] = pk2(0.f, 0.f); }

    const int c0 = cb * 128;
    for (int ch = 0; ch < 12; ch++) {
        const int kb = ks * 384 + ch * 32;
        #pragma unroll
        for (int i = 0; i < 2; i++) {
            int l = tid * 2 + i;
            int row = l >> 3, kq = l & 7;
            float4 v;
            if (kb < 512) v = *(const float4*)&emb[(size_t)stok[row] * EMBD + kb + kq * 4];
            else          v = *(const float4*)&g_h[row * HID + (kb - 512) + kq * 4];
            As[kq * 4 + 0][row] = v.x; As[kq * 4 + 1][row] = v.y;
            As[kq * 4 + 2][row] = v.z; As[kq * 4 + 3][row] = v.w;
        }
        #pragma unroll
        for (int i = 0; i < 4; i++) {
            int l = tid * 4 + i;
            int c = l >> 3, kq = l & 7;
            float4 v;
            if (kb < 512) v = *(const float4*)&wih[(size_t)(c0 + c) * EMBD + kb + kq * 4];
            else          v = *(const float4*)&whh[(size_t)(c0 + c) * HID + (kb - 512) + kq * 4];
            Bs[kq * 4 + 0][c] = v.x; Bs[kq * 4 + 1][c] = v.y;
            Bs[kq * 4 + 2][c] = v.z; Bs[kq * 4 + 3][c] = v.w;
        }
        __syncthreads();
        #pragma unroll 4
        for (int k = 0; k < 32; k++) {
            float4 a0 = *(const float4*)&As[k][ty * 8];
            float4 a1 = *(const float4*)&As[k][ty * 8 + 4];
            float4 b  = *(const float4*)&Bs[k][tx * 4];
            u64 p0 = pk2(b.x, b.y), p1 = pk2(b.z, b.w);
            float ar[8] = {a0.x, a0.y, a0.z, a0.w, a1.x, a1.y, a1.z, a1.w};
            #pragma unroll
            for (int r = 0; r < 8; r++) {
                u64 aa = pk2(ar[r], ar[r]);
                fma2(acc[r][0], aa, p0);
                fma2(acc[r][1], aa, p1);
            }
        }
        __syncthreads();
    }
    float* dst = g_gpart + (size_t)ks * BB * NG;
    #pragma unroll
    for (int r = 0; r < 8; r++) {
        int row = ty * 8 + r;
        float2 v0 = upk2(acc[r][0]), v1 = upk2(acc[r][1]);
        float4 o = make_float4(v0.x, v0.y, v1.x, v1.y);
        *(float4*)&dst[(size_t)row * NG + c0 + tx * 4] = o;
    }
}

// ---------------- LSTM pointwise + fp16 split of new h ----------------------
__global__ void k_lstm(const float* __restrict__ bih,
                       const float* __restrict__ bhh) {
    int idx = blockIdx.x * 256 + threadIdx.x;
    int r = idx >> 10;
    int u = idx & (HID - 1);
    float gv[4];
    #pragma unroll
    for (int g = 0; g < 4; g++) {
        int col = g * HID + u;
        float s = bih[col] + bhh[col];
        const float* p = g_gpart + (size_t)r * NG + col;
        #pragma unroll
        for (int ks = 0; ks < 4; ks++) s += p[(size_t)ks * BB * NG];
        gv[g] = s;
    }
    float ig = 1.f / (1.f + expf(-gv[0]));
    float fg = 1.f / (1.f + expf(-gv[1]));
    float gg = tanhf(gv[2]);
    float og = 1.f / (1.f + expf(-gv[3]));
    float c2 = fg * g_c[idx] + ig * gg;
    float h2 = og * tanhf(c2);
    g_c[idx] = c2;
    g_h[idx] = h2;
    __half hh = __float2half_rn(h2);
    g_hh[idx] = hh;
    g_hl[idx] = __float2half_rn((h2 - __half2float(hh)) * 256.0f);
}

// ---------------- logits: split-fp16 mma.sync + fused argmax ----------------
// 125 CTAs x 512 thr (16 warps as 2(M) x 8(N); 32x32 per warp).
// D[64x256] = Ahi*Bhi + (Ahi*Blo + Alo*Bhi)/256, bias added in epilogue.
__global__ void __launch_bounds__(512, 1)
k_logits(const float* __restrict__ fcb, float* __restrict__ out, int t) {
    extern __shared__ char dsm[];
    const u32 smem0 = smem_u32(dsm);
    const u32 base  = (smem0 + 1023) & ~1023u;
    char* dbase = dsm + (base - smem0);
    float* biasF = (float*)dbase;               // 256 floats
    float* spv   = (float*)(dbase + 1024);      // [64 rows][8 wn]
    int*   spi   = (int*)  (dbase + 3072);      // [64 rows][8 wn]
    const u32 sbase = base + HDR;               // tile buffers (1024-aligned)

    const int tid  = threadIdx.x;
    const int wid  = tid >> 5;
    const int lane = tid & 31;
    const int wm   = wid >> 3;        // 0..1  (32 M-rows each)
    const int wn   = wid & 7;         // 0..7  (32 N-cols each)
    const int v0   = blockIdx.x * 256;

    if (tid < 256) biasF[tid] = fcb[v0 + tid];

    // ---- cp.async fill: 10 x 16B per thread per chunk ----
    const int frow = tid >> 3, fkq = tid & 7;
    auto fill = [&](int ch, int b) {
        const int kb = ch * 64;
        const u32 buf = sbase + b * BUFSTR;
        const u32 swA = SWZ((u32)(frow * 128 + fkq * 16));
        cpa16(buf + AHI_OFF + swA, g_hh + frow * HID + kb + fkq * 8);
        cpa16(buf + ALO_OFF + swA, g_hl + frow * HID + kb + fkq * 8);
        #pragma unroll
        for (int i = 0; i < 4; i++) {
            int row = frow + i * 64;
            u32 sw = SWZ((u32)(row * 128 + fkq * 16));
            cpa16(buf + BHI_OFF + sw, g_whi + (size_t)(v0 + row) * HID + kb + fkq * 8);
            cpa16(buf + BLO_OFF + sw, g_wlo + (size_t)(v0 + row) * HID + kb + fkq * 8);
        }
        CPA_COMMIT();
    };

    float D0[2][4][4], D1[2][4][4];
    #pragma unroll
    for (int a = 0; a < 2; a++)
        #pragma unroll
        for (int b = 0; b < 4; b++)
            #pragma unroll
            for (int c = 0; c < 4; c++) { D0[a][b][c] = 0.f; D1[a][b][c] = 0.f; }

    // per-lane ldmatrix row/col components (byte offsets within a 128B row)
    const int aRow = (lane & 7) + ((lane & 8) ? 8 : 0);   // + 16*tm + 32*wm
    const int aCol = (lane & 16) ? 16 : 0;                // + 32*k16
    const int bRow = (lane & 7) + ((lane & 16) ? 8 : 0);  // + 16*g + 32*wn
    const int bCol = (lane & 8) ? 16 : 0;

    fill(0, 0);
    CPA_WAIT0();
    __syncthreads();

    for (int ch = 0; ch < NCHUNK; ch++) {
        const int b = ch & 1;
        if (ch + 1 < NCHUNK) fill(ch + 1, b ^ 1);

        const u32 buf = sbase + b * BUFSTR;
        #pragma unroll
        for (int k16 = 0; k16 < 4; k16++) {
            const int kkb = k16 * 32;
            u32 ahi[2][4], alo[2][4];
            #pragma unroll
            for (int tm = 0; tm < 2; tm++) {
                u32 off = SWZ((u32)((32 * wm + 16 * tm + aRow) * 128 + kkb + aCol));
                ldm4(ahi[tm], buf + AHI_OFF + off);
                ldm4(alo[tm], buf + ALO_OFF + off);
            }
            #pragma unroll
            for (int g = 0; g < 2; g++) {
                u32 off = SWZ((u32)((32 * wn + 16 * g + bRow) * 128 + kkb + bCol));
                u32 bhi[4], blo[4];
                ldm4(bhi, buf + BHI_OFF + off);
                ldm4(blo, buf + BLO_OFF + off);
                #pragma unroll
                for (int tm = 0; tm < 2; tm++) {
                    #pragma unroll
                    for (int h = 0; h < 2; h++) {
                        int tn = 2 * g + h;
                        mma16816(D0[tm][tn], ahi[tm], &bhi[2 * h]);
                        mma16816(D1[tm][tn], ahi[tm], &blo[2 * h]);
                        mma16816(D1[tm][tn], alo[tm], &bhi[2 * h]);
                    }
                }
            }
        }
        if (ch + 1 < NCHUNK) { CPA_WAIT0(); __syncthreads(); }
    }

    // ---- epilogue: combine, bias, store, per-row argmax ----
    const int q  = lane >> 2;
    const int c2 = (lane & 3) * 2;
    float mv[4] = {-3.4e38f, -3.4e38f, -3.4e38f, -3.4e38f};
    int   mi[4] = {0, 0, 0, 0};
    #pragma unroll
    for (int tm = 0; tm < 2; tm++) {
        int r0 = 32 * wm + 16 * tm + q;
        int r1 = r0 + 8;
        float* p0 = out + (size_t)r0 * TSTEPS * VOC + (size_t)t * VOC + v0;
        float* p1 = out + (size_t)r1 * TSTEPS * VOC + (size_t)t * VOC + v0;
        const int s0 = 2 * tm, s1 = 2 * tm + 1;
        #pragma unroll
        for (int tn = 0; tn < 4; tn++) {
            int c = 32 * wn + 8 * tn + c2;
            float b0 = biasF[c], b1 = biasF[c + 1];
            float v00 = D0[tm][tn][0] + D1[tm][tn][0] * INV256 + b0;
            float v01 = D0[tm][tn][1] + D1[tm][tn][1] * INV256 + b1;
            float v10 = D0[tm][tn][2] + D1[tm][tn][2] * INV256 + b0;
            float v11 = D0[tm][tn][3] + D1[tm][tn][3] * INV256 + b1;
            *(float2*)&p0[c] = make_float2(v00, v01);
            *(float2*)&p1[c] = make_float2(v10, v11);
            int gi = v0 + c;
            if (v00 > mv[s0]) { mv[s0] = v00; mi[s0] = gi; }
            if (v01 > mv[s0]) { mv[s0] = v01; mi[s0] = gi + 1; }
            if (v10 > mv[s1]) { mv[s1] = v10; mi[s1] = gi; }
            if (v11 > mv[s1]) { mv[s1] = v11; mi[s1] = gi + 1; }
        }
    }
    // reduce the 4 quad-lanes holding the same rows (first-index tie break)
    #pragma unroll
    for (int off = 1; off <= 2; off <<= 1) {
        #pragma unroll
        for (int s = 0; s < 4; s++) {
            float ov = __shfl_xor_sync(0xffffffffu, mv[s], off);
            int   oi = __shfl_xor_sync(0xffffffffu, mi[s], off);
            if (ov > mv[s] || (ov == mv[s] && oi < mi[s])) { mv[s] = ov; mi[s] = oi; }
        }
    }
    // per-warp partials -> smem [row][wn], then cross-warp reduce
    if ((lane & 3) == 0) {
        const int rows[4] = {32 * wm + q, 32 * wm + q + 8,
                             32 * wm + 16 + q, 32 * wm + 24 + q};
        #pragma unroll
        for (int s = 0; s < 4; s++) {
            spv[rows[s] * 8 + wn] = mv[s];
            spi[rows[s] * 8 + wn] = mi[s];
        }
    }
    __syncthreads();
    if (tid < 64) {
        float bv = spv[tid * 8]; int bi = spi[tid * 8];
        #pragma unroll
        for (int j = 1; j < 8; j++) {
            float v = spv[tid * 8 + j];
            int   i = spi[tid * 8 + j];
            if (v > bv || (v == bv && i < bi)) { bv = v; bi = i; }
        }
        g_pval[tid * NLBLK + blockIdx.x] = bv;
        g_pidx[tid * NLBLK + blockIdx.x] = bi;
    }
}

// ---------------- final argmax reduce ---------------------------------------
__global__ void k_argmax() {
    int tid = threadIdx.x;              // 256
    int r = tid >> 2, q = tid & 3;
    float bv = -3.4e38f; int bi = 0x7fffffff;
    for (int b = q; b < NLBLK; b += 4) {
        float v = g_pval[r * NLBLK + b];
        int   i = g_pidx[r * NLBLK + b];
        if (v > bv || (v == bv && i < bi)) { bv = v; bi = i; }
    }
    #pragma unroll
    for (int off = 1; off <= 2; off <<= 1) {
        float ov = __shfl_xor_sync(0xffffffffu, bv, off);
        int   oi = __shfl_xor_sync(0xffffffffu, bi, off);
        if (ov > bv || (ov == bv && oi < bi)) { bv = ov; bi = oi; }
    }
    if (q == 0) g_tok[r] = bi;
}

// ---------------- launch -----------------------------------------------------
extern "C" void kernel_launch(void* const* d_in, const int* in_sizes, int n_in,
                              void* d_out, int out_size) {
    const float* z   = (const float*)d_in[0];
    const float* emb = (const float*)d_in[1];
    const float* wih = (const float*)d_in[2];
    const float* whh = (const float*)d_in[3];
    const float* bih = (const float*)d_in[4];
    const float* bhh = (const float*)d_in[5];
    const float* fcw = (const float*)d_in[6];
    const float* fcb = (const float*)d_in[7];
    const float* lw  = (const float*)d_in[8];
    const float* lb  = (const float*)d_in[9];
    float* out = (float*)d_out;

    static int smem_set = 0;
    if (!smem_set) {
        cudaFuncSetAttribute(k_logits, cudaFuncAttributeMaxDynamicSharedMemorySize, DSMEM);
        smem_set = 1;
    }

    k_init<<<256, 256>>>(z, lw, lb);
    k_prep<<<VOC * HID / 1024, 256>>>(fcw);
    for (int t = 0; t < TSTEPS; t++) {
        k_gates<<<dim3(32, 4), 256>>>(emb, wih, whh);
        k_lstm<<<256, 256>>>(bih, bhh);
        k_logits<<<NLBLK, 512, DSMEM>>>(fcb, out, t);
        if (t < TSTEPS - 1) k_argmax<<<1, 256>>>();
    }
}

// round 6
// speedup vs baseline: 3.0224x; 1.0822x over previous
#include <cuda_runtime.h>
#include <cuda_fp16.h>
#include <math.h>

#define BB     64
#define LATENT 128
#define EMBD   512
#define HID    1024
#define VOC    32000
#define TSTEPS 64
#define NLBLK  125          // logits CTAs (125 * 256 = 32000)
#define NCHUNK 16           // logits K chunks of 64 halves
#define NCHG   24           // gates K chunks (1536/64)
#define INV256 0.00390625f

typedef unsigned long long u64;
typedef unsigned int u32;

// ---------------- device state (no allocation) ------------------------------
__device__ float g_c[BB * HID];
__device__ float g_pval[BB * NLBLK];
__device__ int   g_pidx[BB * NLBLK];
__device__ __align__(16) __half g_hhb[2][BB * HID];        // h hi ping-pong
__device__ __align__(16) __half g_hlb[2][BB * HID];        // h lo ping-pong
__device__ __align__(16) __half g_whi[(size_t)VOC * HID];  // fc_w hi
__device__ __align__(16) __half g_wlo[(size_t)VOC * HID];  // fc_w lo*256
__device__ __align__(16) __half g_ehi[(size_t)VOC * EMBD]; // emb hi
__device__ __align__(16) __half g_elo[(size_t)VOC * EMBD]; // emb lo*256
__device__ __align__(16) __half g_pwhi[4096 * 1536];       // packed gate W hi
__device__ __align__(16) __half g_pwlo[4096 * 1536];       // packed gate W lo*256
__device__ float g_pb[4096];                               // packed bih+bhh

// ---------------- helpers ---------------------------------------------------
__device__ __forceinline__ u32 smem_u32(const void* p) {
    u32 a; asm("{ .reg .u64 t; cvta.to.shared.u64 t, %1; cvt.u32.u64 %0, t; }"
               : "=r"(a) : "l"(p));
    return a;
}
__device__ __forceinline__ void cpa16(u32 dst, const void* src) {
    asm volatile("cp.async.cg.shared.global [%0], [%1], 16;" :: "r"(dst), "l"(src));
}
#define CPA_COMMIT() asm volatile("cp.async.commit_group;" ::: "memory")
#define CPA_WAIT0()  asm volatile("cp.async.wait_group 0;" ::: "memory")

__device__ __forceinline__ void ldm4(u32* r, u32 addr) {
    asm volatile("ldmatrix.sync.aligned.m8n8.x4.shared.b16 {%0,%1,%2,%3}, [%4];"
        : "=r"(r[0]), "=r"(r[1]), "=r"(r[2]), "=r"(r[3]) : "r"(addr));
}
__device__ __forceinline__ void mma16816(float* d, const u32* a, const u32* b) {
    asm volatile("mma.sync.aligned.m16n8k16.row.col.f32.f16.f16.f32 "
        "{%0,%1,%2,%3}, {%4,%5,%6,%7}, {%8,%9}, {%0,%1,%2,%3};"
        : "+f"(d[0]), "+f"(d[1]), "+f"(d[2]), "+f"(d[3])
        : "r"(a[0]), "r"(a[1]), "r"(a[2]), "r"(a[3]), "r"(b[0]), "r"(b[1]));
}

#define SWZ(o) ((o) ^ (((o) >> 3) & 0x70))

// logits SMEM: hdr 5120 (bias 1024 | spv 2048 | spi 2048) + 2 buffers
#define AHI_OFF  0
#define ALO_OFF  8192
#define BHI_OFF  16384
#define BLO_OFF  49152
#define BUFSTR   81920
#define HDR      5120
#define DSMEM    (1024 + HDR + 2 * BUFSTR)

// gates SMEM: hdr 1024 (stok 256 | bias 512) + 2 buffers of 48K
#define GAHI 0
#define GALO 8192
#define GBHI 16384
#define GBLO 32768
#define GBUF 49152
#define GHDR 1024
#define GDSM (1024 + GHDR + 2 * GBUF)

// ---------------- init: h = z @ lth_w^T + lth_b -> buf 0 --------------------
__global__ void k_init(const float* __restrict__ z,
                       const float* __restrict__ lw,
                       const float* __restrict__ lb) {
    int idx = blockIdx.x * 256 + threadIdx.x;
    int r = idx >> 10;
    int u = idx & (HID - 1);
    float s = lb[u];
    const float* zr = z + r * LATENT;
    const float* wr = lw + (size_t)u * LATENT;
    #pragma unroll 8
    for (int k = 0; k < LATENT; k++) s += zr[k] * wr[k];
    g_c[idx] = 0.f;
    __half hh = __float2half_rn(s);
    g_hhb[0][idx] = hh;
    g_hlb[0][idx] = __float2half_rn((s - __half2float(hh)) * 256.0f);
}

// ---------------- prep: split fc_w ------------------------------------------
__global__ void k_prep(const float* __restrict__ fcw) {
    size_t i4 = ((size_t)blockIdx.x * 256 + threadIdx.x) * 4;
    float4 w = *(const float4*)&fcw[i4];
    __half h0 = __float2half_rn(w.x), h1 = __float2half_rn(w.y);
    __half h2 = __float2half_rn(w.z), h3 = __float2half_rn(w.w);
    *(__half2*)&g_whi[i4]     = __halves2half2(h0, h1);
    *(__half2*)&g_whi[i4 + 2] = __halves2half2(h2, h3);
    *(__half2*)&g_wlo[i4]     = __halves2half2(
        __float2half_rn((w.x - __half2float(h0)) * 256.f),
        __float2half_rn((w.y - __half2float(h1)) * 256.f));
    *(__half2*)&g_wlo[i4 + 2] = __halves2half2(
        __float2half_rn((w.z - __half2float(h2)) * 256.f),
        __float2half_rn((w.w - __half2float(h3)) * 256.f));
}

// ---------------- prep: split emb -------------------------------------------
__global__ void k_prep_emb(const float* __restrict__ emb) {
    size_t i4 = ((size_t)blockIdx.x * 256 + threadIdx.x) * 4;
    float4 w = *(const float4*)&emb[i4];
    __half h0 = __float2half_rn(w.x), h1 = __float2half_rn(w.y);
    __half h2 = __float2half_rn(w.z), h3 = __float2half_rn(w.w);
    *(__half2*)&g_ehi[i4]     = __halves2half2(h0, h1);
    *(__half2*)&g_ehi[i4 + 2] = __halves2half2(h2, h3);
    *(__half2*)&g_elo[i4]     = __halves2half2(
        __float2half_rn((w.x - __half2float(h0)) * 256.f),
        __float2half_rn((w.y - __half2float(h1)) * 256.f));
    *(__half2*)&g_elo[i4 + 2] = __halves2half2(
        __float2half_rn((w.z - __half2float(h2)) * 256.f),
        __float2half_rn((w.w - __half2float(h3)) * 256.f));
}

// ---------------- prep: pack gate weights (permuted) + bias -----------------
// dst row cn = c*128 + n;  n -> gate g=n>>5, j=n&31;  orow = g*1024 + c*32 + j
// virtual k: [0,512) = w_ih, [512,1536) = w_hh
__global__ void k_prep_w(const float* __restrict__ wih,
                         const float* __restrict__ whh,
                         const float* __restrict__ bih,
                         const float* __restrict__ bhh) {
    int cn = blockIdx.x;                 // 0..4095
    int c = cn >> 7, n = cn & 127;
    int g = n >> 5, j = n & 31;
    int orow = g * 1024 + c * 32 + j;
    int k0 = threadIdx.x * 4;            // 0..1532
    float4 w = (k0 < 512)
        ? *(const float4*)&wih[(size_t)orow * EMBD + k0]
        : *(const float4*)&whh[(size_t)orow * HID + k0 - 512];
    size_t d = (size_t)cn * 1536 + k0;
    __half h0 = __float2half_rn(w.x), h1 = __float2half_rn(w.y);
    __half h2 = __float2half_rn(w.z), h3 = __float2half_rn(w.w);
    *(__half2*)&g_pwhi[d]     = __halves2half2(h0, h1);
    *(__half2*)&g_pwhi[d + 2] = __halves2half2(h2, h3);
    *(__half2*)&g_pwlo[d]     = __halves2half2(
        __float2half_rn((w.x - __half2float(h0)) * 256.f),
        __float2half_rn((w.y - __half2float(h1)) * 256.f));
    *(__half2*)&g_pwlo[d + 2] = __halves2half2(
        __float2half_rn((w.z - __half2float(h2)) * 256.f),
        __float2half_rn((w.w - __half2float(h3)) * 256.f));
    if (threadIdx.x == 0) g_pb[cn] = bih[orow] + bhh[orow];
}

// ---------------- fused gates MMA + LSTM + argmax-prologue ------------------
// 32 CTAs x 256 thr (8 warps: 2(M) x 4(N), 32x32 each). CTA c owns u in
// [32c, 32c+32): computes all 4 gates, applies LSTM, writes h[p^1] hi/lo.
__global__ void __launch_bounds__(256, 1)
k_gatelstm(int t) {
    extern __shared__ char dsm[];
    const u32 smem0 = smem_u32(dsm);
    const u32 base  = (smem0 + 1023) & ~1023u;
    char* dbase = dsm + (base - smem0);
    int*   stok  = (int*)dbase;                  // 64
    float* biasG = (float*)(dbase + 256);        // 128
    float* sg    = (float*)(dbase + GHDR);       // overlay buf0: [64][129]
    const u32 sbase = base + GHDR;

    const int tid  = threadIdx.x;
    const int wid  = tid >> 5;
    const int lane = tid & 31;
    const int wm   = wid >> 2;        // 0..1
    const int wn   = wid & 3;         // 0..3
    const int cta  = blockIdx.x;
    const int rp   = t & 1;           // read h parity
    const int wp   = rp ^ 1;

    // token argmax from previous step's partials (redundant across CTAs)
    if (t == 0) {
        if (tid < BB) stok[tid] = 0;
    } else {
        int r = tid >> 2, q4 = tid & 3;
        float bv = -3.4e38f; int bi = 0x7fffffff;
        for (int b = q4; b < NLBLK; b += 4) {
            float v = g_pval[r * NLBLK + b];
            int   i = g_pidx[r * NLBLK + b];
            if (v > bv || (v == bv && i < bi)) { bv = v; bi = i; }
        }
        #pragma unroll
        for (int off = 1; off <= 2; off <<= 1) {
            float ov = __shfl_xor_sync(0xffffffffu, bv, off);
            int   oi = __shfl_xor_sync(0xffffffffu, bi, off);
            if (ov > bv || (ov == bv && oi < bi)) { bv = ov; bi = oi; }
        }
        if (q4 == 0) stok[r] = bi;
    }
    if (tid < 128) biasG[tid] = g_pb[cta * 128 + tid];
    __syncthreads();

    // ---- cp.async fill: A 64 rows (emb/h), B 128 packed weight rows --------
    const int frow = tid >> 3, fkq = tid & 7;   // frow 0..31
    auto fill = [&](int ch, int b) {
        const int kb = ch * 64;
        const u32 buf = sbase + b * GBUF;
        #pragma unroll
        for (int i = 0; i < 2; i++) {           // A rows frow, frow+32
            int row = frow + i * 32;
            u32 sw = SWZ((u32)(row * 128 + fkq * 16));
            if (kb < 512) {
                const size_t s = (size_t)stok[row] * EMBD + kb + fkq * 8;
                cpa16(buf + GAHI + sw, g_ehi + s);
                cpa16(buf + GALO + sw, g_elo + s);
            } else {
                const size_t s = (size_t)row * HID + (kb - 512) + fkq * 8;
                cpa16(buf + GAHI + sw, g_hhb[rp] + s);
                cpa16(buf + GALO + sw, g_hlb[rp] + s);
            }
        }
        #pragma unroll
        for (int i = 0; i < 4; i++) {           // B rows frow + i*32
            int row = frow + i * 32;
            u32 sw = SWZ((u32)(row * 128 + fkq * 16));
            const size_t s = (size_t)(cta * 128 + row) * 1536 + kb + fkq * 8;
            cpa16(buf + GBHI + sw, g_pwhi + s);
            cpa16(buf + GBLO + sw, g_pwlo + s);
        }
        CPA_COMMIT();
    };

    float D0[2][4][4], D1[2][4][4];
    #pragma unroll
    for (int a = 0; a < 2; a++)
        #pragma unroll
        for (int b = 0; b < 4; b++)
            #pragma unroll
            for (int cc = 0; cc < 4; cc++) { D0[a][b][cc] = 0.f; D1[a][b][cc] = 0.f; }

    const int aRow = (lane & 7) + ((lane & 8) ? 8 : 0);
    const int aCol = (lane & 16) ? 16 : 0;
    const int bRow = (lane & 7) + ((lane & 16) ? 8 : 0);
    const int bCol = (lane & 8) ? 16 : 0;

    fill(0, 0);
    CPA_WAIT0();
    __syncthreads();

    for (int ch = 0; ch < NCHG; ch++) {
        const int b = ch & 1;
        if (ch + 1 < NCHG) fill(ch + 1, b ^ 1);
        const u32 buf = sbase + b * GBUF;
        #pragma unroll
        for (int k16 = 0; k16 < 4; k16++) {
            const int kkb = k16 * 32;
            u32 ahi[2][4], alo[2][4];
            #pragma unroll
            for (int tm = 0; tm < 2; tm++) {
                u32 off = SWZ((u32)((32 * wm + 16 * tm + aRow) * 128 + kkb + aCol));
                ldm4(ahi[tm], buf + GAHI + off);
                ldm4(alo[tm], buf + GALO + off);
            }
            #pragma unroll
            for (int g = 0; g < 2; g++) {
                u32 off = SWZ((u32)((32 * wn + 16 * g + bRow) * 128 + kkb + bCol));
                u32 bhi[4], blo[4];
                ldm4(bhi, buf + GBHI + off);
                ldm4(blo, buf + GBLO + off);
                #pragma unroll
                for (int tm = 0; tm < 2; tm++) {
                    #pragma unroll
                    for (int h = 0; h < 2; h++) {
                        int tn = 2 * g + h;
                        mma16816(D0[tm][tn], ahi[tm], &bhi[2 * h]);
                        mma16816(D1[tm][tn], ahi[tm], &blo[2 * h]);
                        mma16816(D1[tm][tn], alo[tm], &bhi[2 * h]);
                    }
                }
            }
        }
        if (ch + 1 < NCHG) { CPA_WAIT0(); __syncthreads(); }
    }

    // ---- deposit gates to smem [64 rows][129] (overlay buf0, safe) ---------
    const int q  = lane >> 2;
    const int c2 = (lane & 3) * 2;
    #pragma unroll
    for (int tm = 0; tm < 2; tm++) {
        int r0 = 32 * wm + 16 * tm + q;
        int r1 = r0 + 8;
        #pragma unroll
        for (int tn = 0; tn < 4; tn++) {
            int c = 32 * wn + 8 * tn + c2;
            float b0 = biasG[c], b1 = biasG[c + 1];
            sg[r0 * 129 + c]     = D0[tm][tn][0] + D1[tm][tn][0] * INV256 + b0;
            sg[r0 * 129 + c + 1] = D0[tm][tn][1] + D1[tm][tn][1] * INV256 + b1;
            sg[r1 * 129 + c]     = D0[tm][tn][2] + D1[tm][tn][2] * INV256 + b0;
            sg[r1 * 129 + c + 1] = D0[tm][tn][3] + D1[tm][tn][3] * INV256 + b1;
        }
    }
    __syncthreads();

    // ---- LSTM pointwise: thread -> row tid>>2, u' = (tid&3)*8 .. +7 --------
    {
        const int row = tid >> 2;
        const int up0 = (tid & 3) * 8;
        const float* sgp = sg + row * 129;
        #pragma unroll
        for (int i = 0; i < 8; i++) {
            int up = up0 + i;
            float gi = sgp[up];
            float gf = sgp[32 + up];
            float gg = sgp[64 + up];
            float go = sgp[96 + up];
            float ig = 1.f / (1.f + expf(-gi));
            float fg = 1.f / (1.f + expf(-gf));
            float gt = tanhf(gg);
            float og = 1.f / (1.f + expf(-go));
            int idx = row * HID + cta * 32 + up;
            float cv = fg * g_c[idx] + ig * gt;
            float hv = og * tanhf(cv);
            g_c[idx] = cv;
            __half hh = __float2half_rn(hv);
            g_hhb[wp][idx] = hh;
            g_hlb[wp][idx] = __float2half_rn((hv - __half2float(hh)) * 256.0f);
        }
    }
}

// ---------------- logits: split-fp16 mma.sync + fused argmax ----------------
__global__ void __launch_bounds__(512, 1)
k_logits(const float* __restrict__ fcb, float* __restrict__ out, int t) {
    extern __shared__ char dsm[];
    const u32 smem0 = smem_u32(dsm);
    const u32 base  = (smem0 + 1023) & ~1023u;
    char* dbase = dsm + (base - smem0);
    float* biasF = (float*)dbase;
    float* spv   = (float*)(dbase + 1024);
    int*   spi   = (int*)  (dbase + 3072);
    const u32 sbase = base + HDR;

    const int tid  = threadIdx.x;
    const int wid  = tid >> 5;
    const int lane = tid & 31;
    const int wm   = wid >> 3;
    const int wn   = wid & 7;
    const int v0   = blockIdx.x * 256;
    const int hp   = (t & 1) ^ 1;      // h parity written by gates this step

    if (tid < 256) biasF[tid] = fcb[v0 + tid];

    const int frow = tid >> 3, fkq = tid & 7;
    auto fill = [&](int ch, int b) {
        const int kb = ch * 64;
        const u32 buf = sbase + b * BUFSTR;
        const u32 swA = SWZ((u32)(frow * 128 + fkq * 16));
        cpa16(buf + AHI_OFF + swA, g_hhb[hp] + frow * HID + kb + fkq * 8);
        cpa16(buf + ALO_OFF + swA, g_hlb[hp] + frow * HID + kb + fkq * 8);
        #pragma unroll
        for (int i = 0; i < 4; i++) {
            int row = frow + i * 64;
            u32 sw = SWZ((u32)(row * 128 + fkq * 16));
            cpa16(buf + BHI_OFF + sw, g_whi + (size_t)(v0 + row) * HID + kb + fkq * 8);
            cpa16(buf + BLO_OFF + sw, g_wlo + (size_t)(v0 + row) * HID + kb + fkq * 8);
        }
        CPA_COMMIT();
    };

    float D0[2][4][4], D1[2][4][4];
    #pragma unroll
    for (int a = 0; a < 2; a++)
        #pragma unroll
        for (int b = 0; b < 4; b++)
            #pragma unroll
            for (int c = 0; c < 4; c++) { D0[a][b][c] = 0.f; D1[a][b][c] = 0.f; }

    const int aRow = (lane & 7) + ((lane & 8) ? 8 : 0);
    const int aCol = (lane & 16) ? 16 : 0;
    const int bRow = (lane & 7) + ((lane & 16) ? 8 : 0);
    const int bCol = (lane & 8) ? 16 : 0;

    fill(0, 0);
    CPA_WAIT0();
    __syncthreads();

    for (int ch = 0; ch < NCHUNK; ch++) {
        const int b = ch & 1;
        if (ch + 1 < NCHUNK) fill(ch + 1, b ^ 1);
        const u32 buf = sbase + b * BUFSTR;
        #pragma unroll
        for (int k16 = 0; k16 < 4; k16++) {
            const int kkb = k16 * 32;
            u32 ahi[2][4], alo[2][4];
            #pragma unroll
            for (int tm = 0; tm < 2; tm++) {
                u32 off = SWZ((u32)((32 * wm + 16 * tm + aRow) * 128 + kkb + aCol));
                ldm4(ahi[tm], buf + AHI_OFF + off);
                ldm4(alo[tm], buf + ALO_OFF + off);
            }
            #pragma unroll
            for (int g = 0; g < 2; g++) {
                u32 off = SWZ((u32)((32 * wn + 16 * g + bRow) * 128 + kkb + bCol));
                u32 bhi[4], blo[4];
                ldm4(bhi, buf + BHI_OFF + off);
                ldm4(blo, buf + BLO_OFF + off);
                #pragma unroll
                for (int tm = 0; tm < 2; tm++) {
                    #pragma unroll
                    for (int h = 0; h < 2; h++) {
                        int tn = 2 * g + h;
                        mma16816(D0[tm][tn], ahi[tm], &bhi[2 * h]);
                        mma16816(D1[tm][tn], ahi[tm], &blo[2 * h]);
                        mma16816(D1[tm][tn], alo[tm], &bhi[2 * h]);
                    }
                }
            }
        }
        if (ch + 1 < NCHUNK) { CPA_WAIT0(); __syncthreads(); }
    }

    const int q  = lane >> 2;
    const int c2 = (lane & 3) * 2;
    float mv[4] = {-3.4e38f, -3.4e38f, -3.4e38f, -3.4e38f};
    int   mi[4] = {0, 0, 0, 0};
    #pragma unroll
    for (int tm = 0; tm < 2; tm++) {
        int r0 = 32 * wm + 16 * tm + q;
        int r1 = r0 + 8;
        float* p0 = out + (size_t)r0 * TSTEPS * VOC + (size_t)t * VOC + v0;
        float* p1 = out + (size_t)r1 * TSTEPS * VOC + (size_t)t * VOC + v0;
        const int s0 = 2 * tm, s1 = 2 * tm + 1;
        #pragma unroll
        for (int tn = 0; tn < 4; tn++) {
            int c = 32 * wn + 8 * tn + c2;
            float b0 = biasF[c], b1 = biasF[c + 1];
            float v00 = D0[tm][tn][0] + D1[tm][tn][0] * INV256 + b0;
            float v01 = D0[tm][tn][1] + D1[tm][tn][1] * INV256 + b1;
            float v10 = D0[tm][tn][2] + D1[tm][tn][2] * INV256 + b0;
            float v11 = D0[tm][tn][3] + D1[tm][tn][3] * INV256 + b1;
            *(float2*)&p0[c] = make_float2(v00, v01);
            *(float2*)&p1[c] = make_float2(v10, v11);
            int gi = v0 + c;
            if (v00 > mv[s0]) { mv[s0] = v00; mi[s0] = gi; }
            if (v01 > mv[s0]) { mv[s0] = v01; mi[s0] = gi + 1; }
            if (v10 > mv[s1]) { mv[s1] = v10; mi[s1] = gi; }
            if (v11 > mv[s1]) { mv[s1] = v11; mi[s1] = gi + 1; }
        }
    }
    #pragma unroll
    for (int off = 1; off <= 2; off <<= 1) {
        #pragma unroll
        for (int s = 0; s < 4; s++) {
            float ov = __shfl_xor_sync(0xffffffffu, mv[s], off);
            int   oi = __shfl_xor_sync(0xffffffffu, mi[s], off);
            if (ov > mv[s] || (ov == mv[s] && oi < mi[s])) { mv[s] = ov; mi[s] = oi; }
        }
    }
    if ((lane & 3) == 0) {
        const int rows[4] = {32 * wm + q, 32 * wm + q + 8,
                             32 * wm + 16 + q, 32 * wm + 24 + q};
        #pragma unroll
        for (int s = 0; s < 4; s++) {
            spv[rows[s] * 8 + wn] = mv[s];
            spi[rows[s] * 8 + wn] = mi[s];
        }
    }
    __syncthreads();
    if (tid < 64) {
        float bv = spv[tid * 8]; int bi = spi[tid * 8];
        #pragma unroll
        for (int j = 1; j < 8; j++) {
            float v = spv[tid * 8 + j];
            int   i = spi[tid * 8 + j];
            if (v > bv || (v == bv && i < bi)) { bv = v; bi = i; }
        }
        g_pval[tid * NLBLK + blockIdx.x] = bv;
        g_pidx[tid * NLBLK + blockIdx.x] = bi;
    }
}

// ---------------- launch -----------------------------------------------------
extern "C" void kernel_launch(void* const* d_in, const int* in_sizes, int n_in,
                              void* d_out, int out_size) {
    const float* z   = (const float*)d_in[0];
    const float* emb = (const float*)d_in[1];
    const float* wih = (const float*)d_in[2];
    const float* whh = (const float*)d_in[3];
    const float* bih = (const float*)d_in[4];
    const float* bhh = (const float*)d_in[5];
    const float* fcw = (const float*)d_in[6];
    const float* fcb = (const float*)d_in[7];
    const float* lw  = (const float*)d_in[8];
    const float* lb  = (const float*)d_in[9];
    float* out = (float*)d_out;

    static int smem_set = 0;
    if (!smem_set) {
        cudaFuncSetAttribute(k_logits,   cudaFuncAttributeMaxDynamicSharedMemorySize, DSMEM);
        cudaFuncSetAttribute(k_gatelstm, cudaFuncAttributeMaxDynamicSharedMemorySize, GDSM);
        smem_set = 1;
    }

    k_init<<<256, 256>>>(z, lw, lb);
    k_prep<<<VOC * HID / 1024, 256>>>(fcw);
    k_prep_emb<<<VOC * EMBD / 1024, 256>>>(emb);
    k_prep_w<<<4096, 384>>>(wih, whh, bih, bhh);
    for (int t = 0; t < TSTEPS; t++) {
        k_gatelstm<<<32, 256, GDSM>>>(t);
        k_logits<<<NLBLK, 512, DSMEM>>>(fcb, out, t);
    }
}

// round 7
// speedup vs baseline: 3.3418x; 1.1057x over previous
#include <cuda_runtime.h>
#include <cuda_fp16.h>
#include <math.h>

#define BB     64
#define LATENT 128
#define EMBD   512
#define HID    1024
#define VOC    32000
#define TSTEPS 64
#define NLBLK  125          // logits CTAs (125 * 256 = 32000)
#define NCHUNK 16           // logits K chunks of 64 halves
#define NCHG   24           // gates K chunks (1536/64)
#define INV256 0.00390625f

typedef unsigned long long u64;
typedef unsigned int u32;

// ---------------- device state (no allocation) ------------------------------
__device__ float g_c[BB * HID];
__device__ float g_pval[BB * NLBLK];
__device__ int   g_pidx[BB * NLBLK];
__device__ __align__(16) __half g_hhb[2][BB * HID];        // h hi ping-pong
__device__ __align__(16) __half g_hlb[2][BB * HID];        // h lo ping-pong
__device__ __align__(16) __half g_whi[(size_t)VOC * HID];  // fc_w hi
__device__ __align__(16) __half g_wlo[(size_t)VOC * HID];  // fc_w lo*256
__device__ __align__(16) __half g_ehi[(size_t)VOC * EMBD]; // emb hi
__device__ __align__(16) __half g_elo[(size_t)VOC * EMBD]; // emb lo*256
__device__ __align__(16) __half g_pwhi[4096 * 1536];       // packed gate W hi
__device__ __align__(16) __half g_pwlo[4096 * 1536];       // packed gate W lo*256
__device__ float g_pb[4096];                               // packed bih+bhh

// ---------------- helpers ---------------------------------------------------
__device__ __forceinline__ u32 smem_u32(const void* p) {
    u32 a; asm("{ .reg .u64 t; cvta.to.shared.u64 t, %1; cvt.u32.u64 %0, t; }"
               : "=r"(a) : "l"(p));
    return a;
}
__device__ __forceinline__ void cpa16(u32 dst, const void* src) {
    asm volatile("cp.async.cg.shared.global [%0], [%1], 16;" :: "r"(dst), "l"(src));
}
#define CPA_COMMIT() asm volatile("cp.async.commit_group;" ::: "memory")
#define CPA_WAIT0()  asm volatile("cp.async.wait_group 0;" ::: "memory")

__device__ __forceinline__ void ldm4(u32* r, u32 addr) {
    asm volatile("ldmatrix.sync.aligned.m8n8.x4.shared.b16 {%0,%1,%2,%3}, [%4];"
        : "=r"(r[0]), "=r"(r[1]), "=r"(r[2]), "=r"(r[3]) : "r"(addr));
}
__device__ __forceinline__ void mma16816(float* d, const u32* a, const u32* b) {
    asm volatile("mma.sync.aligned.m16n8k16.row.col.f32.f16.f16.f32 "
        "{%0,%1,%2,%3}, {%4,%5,%6,%7}, {%8,%9}, {%0,%1,%2,%3};"
        : "+f"(d[0]), "+f"(d[1]), "+f"(d[2]), "+f"(d[3])
        : "r"(a[0]), "r"(a[1]), "r"(a[2]), "r"(a[3]), "r"(b[0]), "r"(b[1]));
}

#define SWZ(o) ((o) ^ (((o) >> 3) & 0x70))

// logits SMEM: hdr 5120 (bias 1024 | spv 2048 | spi 2048) + 2 buffers
#define AHI_OFF  0
#define ALO_OFF  8192
#define BHI_OFF  16384
#define BLO_OFF  49152
#define BUFSTR   81920
#define HDR      5120
#define DSMEM    (1024 + HDR + 2 * BUFSTR)

// gates SMEM: hdr 512 (stok 256 | bias 128) + 2 buffers of 24K
#define GAHI 0
#define GALO 8192
#define GBHI 16384
#define GBLO 20480
#define GBUF 24576
#define GHDR 512
#define GDSM (1024 + GHDR + 2 * GBUF)

// ---------------- init: h = z @ lth_w^T + lth_b -> buf 0 --------------------
__global__ void k_init(const float* __restrict__ z,
                       const float* __restrict__ lw,
                       const float* __restrict__ lb) {
    int idx = blockIdx.x * 256 + threadIdx.x;
    int r = idx >> 10;
    int u = idx & (HID - 1);
    float s = lb[u];
    const float* zr = z + r * LATENT;
    const float* wr = lw + (size_t)u * LATENT;
    #pragma unroll 8
    for (int k = 0; k < LATENT; k++) s += zr[k] * wr[k];
    g_c[idx] = 0.f;
    __half hh = __float2half_rn(s);
    g_hhb[0][idx] = hh;
    g_hlb[0][idx] = __float2half_rn((s - __half2float(hh)) * 256.0f);
}

// ---------------- prep: split fc_w ------------------------------------------
__global__ void k_prep(const float* __restrict__ fcw) {
    size_t i4 = ((size_t)blockIdx.x * 256 + threadIdx.x) * 4;
    float4 w = *(const float4*)&fcw[i4];
    __half h0 = __float2half_rn(w.x), h1 = __float2half_rn(w.y);
    __half h2 = __float2half_rn(w.z), h3 = __float2half_rn(w.w);
    *(__half2*)&g_whi[i4]     = __halves2half2(h0, h1);
    *(__half2*)&g_whi[i4 + 2] = __halves2half2(h2, h3);
    *(__half2*)&g_wlo[i4]     = __halves2half2(
        __float2half_rn((w.x - __half2float(h0)) * 256.f),
        __float2half_rn((w.y - __half2float(h1)) * 256.f));
    *(__half2*)&g_wlo[i4 + 2] = __halves2half2(
        __float2half_rn((w.z - __half2float(h2)) * 256.f),
        __float2half_rn((w.w - __half2float(h3)) * 256.f));
}

// ---------------- prep: split emb -------------------------------------------
__global__ void k_prep_emb(const float* __restrict__ emb) {
    size_t i4 = ((size_t)blockIdx.x * 256 + threadIdx.x) * 4;
    float4 w = *(const float4*)&emb[i4];
    __half h0 = __float2half_rn(w.x), h1 = __float2half_rn(w.y);
    __half h2 = __float2half_rn(w.z), h3 = __float2half_rn(w.w);
    *(__half2*)&g_ehi[i4]     = __halves2half2(h0, h1);
    *(__half2*)&g_ehi[i4 + 2] = __halves2half2(h2, h3);
    *(__half2*)&g_elo[i4]     = __halves2half2(
        __float2half_rn((w.x - __half2float(h0)) * 256.f),
        __float2half_rn((w.y - __half2float(h1)) * 256.f));
    *(__half2*)&g_elo[i4 + 2] = __halves2half2(
        __float2half_rn((w.z - __half2float(h2)) * 256.f),
        __float2half_rn((w.w - __half2float(h3)) * 256.f));
}

// ---------------- prep: pack gate weights (permuted) + bias -----------------
// dst row cn = c*32 + n;  c in [0,128) owns units [8c, 8c+8)
// n -> gate g=n>>3, j=n&7;  orow = g*1024 + c*8 + j
// virtual k: [0,512) = w_ih, [512,1536) = w_hh
__global__ void k_prep_w(const float* __restrict__ wih,
                         const float* __restrict__ whh,
                         const float* __restrict__ bih,
                         const float* __restrict__ bhh) {
    int cn = blockIdx.x;                 // 0..4095
    int c = cn >> 5, n = cn & 31;
    int g = n >> 3, j = n & 7;
    int orow = g * 1024 + c * 8 + j;
    int k0 = threadIdx.x * 4;            // 0..1532
    float4 w = (k0 < 512)
        ? *(const float4*)&wih[(size_t)orow * EMBD + k0]
        : *(const float4*)&whh[(size_t)orow * HID + k0 - 512];
    size_t d = (size_t)cn * 1536 + k0;
    __half h0 = __float2half_rn(w.x), h1 = __float2half_rn(w.y);
    __half h2 = __float2half_rn(w.z), h3 = __float2half_rn(w.w);
    *(__half2*)&g_pwhi[d]     = __halves2half2(h0, h1);
    *(__half2*)&g_pwhi[d + 2] = __halves2half2(h2, h3);
    *(__half2*)&g_pwlo[d]     = __halves2half2(
        __float2half_rn((w.x - __half2float(h0)) * 256.f),
        __float2half_rn((w.y - __half2float(h1)) * 256.f));
    *(__half2*)&g_pwlo[d + 2] = __halves2half2(
        __float2half_rn((w.z - __half2float(h2)) * 256.f),
        __float2half_rn((w.w - __half2float(h3)) * 256.f));
    if (threadIdx.x == 0) g_pb[cn] = bih[orow] + bhh[orow];
}

// ---------------- fused gates MMA + LSTM + argmax-prologue ------------------
// 128 CTAs x 256 thr (8 warps: 4(M) x 2(N), 16x16 each). CTA c owns units
// [8c, 8c+8): all 4 gates (32 cols), applies LSTM, writes h[p^1] hi/lo.
__global__ void __launch_bounds__(256, 1)
k_gatelstm(int t) {
    extern __shared__ char dsm[];
    const u32 smem0 = smem_u32(dsm);
    const u32 base  = (smem0 + 1023) & ~1023u;
    char* dbase = dsm + (base - smem0);
    int*   stok  = (int*)dbase;                  // 64
    float* biasG = (float*)(dbase + 256);        // 32
    float* sg    = (float*)(dbase + GHDR);       // overlay buf0: [64][33]
    const u32 sbase = base + GHDR;

    const int tid  = threadIdx.x;
    const int wid  = tid >> 5;
    const int lane = tid & 31;
    const int wm   = wid >> 1;        // 0..3 (16 M-rows each)
    const int wn   = wid & 1;         // 0..1 (16 N-cols each)
    const int cta  = blockIdx.x;
    const int rp   = t & 1;           // read h parity
    const int wp   = rp ^ 1;

    // token argmax from previous step's partials (redundant across CTAs)
    if (t == 0) {
        if (tid < BB) stok[tid] = 0;
    } else {
        int r = tid >> 2, q4 = tid & 3;
        float bv = -3.4e38f; int bi = 0x7fffffff;
        for (int b = q4; b < NLBLK; b += 4) {
            float v = g_pval[r * NLBLK + b];
            int   i = g_pidx[r * NLBLK + b];
            if (v > bv || (v == bv && i < bi)) { bv = v; bi = i; }
        }
        #pragma unroll
        for (int off = 1; off <= 2; off <<= 1) {
            float ov = __shfl_xor_sync(0xffffffffu, bv, off);
            int   oi = __shfl_xor_sync(0xffffffffu, bi, off);
            if (ov > bv || (ov == bv && oi < bi)) { bv = ov; bi = oi; }
        }
        if (q4 == 0) stok[r] = bi;
    }
    if (tid < 32) biasG[tid] = g_pb[cta * 32 + tid];
    __syncthreads();

    // ---- cp.async fill: A 64 rows (emb/h), B 32 packed weight rows ---------
    const int arow = tid >> 2, aq = (tid & 3) * 2;   // A: 2 positions each
    const int brow = tid >> 3, bq = tid & 7;         // B: 1 position each
    auto fill = [&](int ch, int b) {
        const int kb = ch * 64;
        const u32 buf = sbase + b * GBUF;
        #pragma unroll
        for (int i = 0; i < 2; i++) {
            int kq = aq + i;
            u32 sw = SWZ((u32)(arow * 128 + kq * 16));
            if (kb < 512) {
                const size_t s = (size_t)stok[arow] * EMBD + kb + kq * 8;
                cpa16(buf + GAHI + sw, g_ehi + s);
                cpa16(buf + GALO + sw, g_elo + s);
            } else {
                const size_t s = (size_t)arow * HID + (kb - 512) + kq * 8;
                cpa16(buf + GAHI + sw, g_hhb[rp] + s);
                cpa16(buf + GALO + sw, g_hlb[rp] + s);
            }
        }
        {
            u32 sw = SWZ((u32)(brow * 128 + bq * 16));
            const size_t s = (size_t)(cta * 32 + brow) * 1536 + kb + bq * 8;
            cpa16(buf + GBHI + sw, g_pwhi + s);
            cpa16(buf + GBLO + sw, g_pwlo + s);
        }
        CPA_COMMIT();
    };

    float D0[2][4], D1[2][4];
    #pragma unroll
    for (int h = 0; h < 2; h++)
        #pragma unroll
        for (int cc = 0; cc < 4; cc++) { D0[h][cc] = 0.f; D1[h][cc] = 0.f; }

    const int aRow = (lane & 7) + ((lane & 8) ? 8 : 0);
    const int aCol = (lane & 16) ? 16 : 0;
    const int bRow = (lane & 7) + ((lane & 16) ? 8 : 0);
    const int bCol = (lane & 8) ? 16 : 0;

    fill(0, 0);
    CPA_WAIT0();
    __syncthreads();

    for (int ch = 0; ch < NCHG; ch++) {
        const int b = ch & 1;
        if (ch + 1 < NCHG) fill(ch + 1, b ^ 1);
        const u32 buf = sbase + b * GBUF;
        #pragma unroll
        for (int k16 = 0; k16 < 4; k16++) {
            const int kkb = k16 * 32;
            u32 ahi[4], alo[4], bhi[4], blo[4];
            u32 offA = SWZ((u32)((16 * wm + aRow) * 128 + kkb + aCol));
            ldm4(ahi, buf + GAHI + offA);
            ldm4(alo, buf + GALO + offA);
            u32 offB = SWZ((u32)((16 * wn + bRow) * 128 + kkb + bCol));
            ldm4(bhi, buf + GBHI + offB);
            ldm4(blo, buf + GBLO + offB);
            #pragma unroll
            for (int h = 0; h < 2; h++) {
                mma16816(D0[h], ahi, &bhi[2 * h]);
                mma16816(D1[h], ahi, &blo[2 * h]);
                mma16816(D1[h], alo, &bhi[2 * h]);
            }
        }
        if (ch + 1 < NCHG) { CPA_WAIT0(); __syncthreads(); }
    }

    // ---- deposit gates to smem [64 rows][33] (overlay buf0, safe) ----------
    const int q  = lane >> 2;
    const int c2 = (lane & 3) * 2;
    {
        int r0 = 16 * wm + q;
        int r1 = r0 + 8;
        #pragma unroll
        for (int h = 0; h < 2; h++) {
            int c = 16 * wn + 8 * h + c2;
            float b0 = biasG[c], b1 = biasG[c + 1];
            sg[r0 * 33 + c]     = D0[h][0] + D1[h][0] * INV256 + b0;
            sg[r0 * 33 + c + 1] = D0[h][1] + D1[h][1] * INV256 + b1;
            sg[r1 * 33 + c]     = D0[h][2] + D1[h][2] * INV256 + b0;
            sg[r1 * 33 + c + 1] = D0[h][3] + D1[h][3] * INV256 + b1;
        }
    }
    __syncthreads();

    // ---- LSTM pointwise: thread -> row tid>>2, units (tid&3)*2, +1 ---------
    {
        const int row = tid >> 2;
        const int j0 = (tid & 3) * 2;
        const float* sgp = sg + row * 33;
        #pragma unroll
        for (int i = 0; i < 2; i++) {
            int j = j0 + i;
            float gi = sgp[j];
            float gf = sgp[8 + j];
            float gg = sgp[16 + j];
            float go = sgp[24 + j];
            float ig = 1.f / (1.f + expf(-gi));
            float fg = 1.f / (1.f + expf(-gf));
            float gt = tanhf(gg);
            float og = 1.f / (1.f + expf(-go));
            int idx = row * HID + cta * 8 + j;
            float cv = fg * g_c[idx] + ig * gt;
            float hv = og * tanhf(cv);
            g_c[idx] = cv;
            __half hh = __float2half_rn(hv);
            g_hhb[wp][idx] = hh;
            g_hlb[wp][idx] = __float2half_rn((hv - __half2float(hh)) * 256.0f);
        }
    }
}

// ---------------- logits: split-fp16 mma.sync + fused argmax ----------------
__global__ void __launch_bounds__(512, 1)
k_logits(const float* __restrict__ fcb, float* __restrict__ out, int t) {
    extern __shared__ char dsm[];
    const u32 smem0 = smem_u32(dsm);
    const u32 base  = (smem0 + 1023) & ~1023u;
    char* dbase = dsm + (base - smem0);
    float* biasF = (float*)dbase;
    float* spv   = (float*)(dbase + 1024);
    int*   spi   = (int*)  (dbase + 3072);
    const u32 sbase = base + HDR;

    const int tid  = threadIdx.x;
    const int wid  = tid >> 5;
    const int lane = tid & 31;
    const int wm   = wid >> 3;
    const int wn   = wid & 7;
    const int v0   = blockIdx.x * 256;
    const int hp   = (t & 1) ^ 1;      // h parity written by gates this step

    if (tid < 256) biasF[tid] = fcb[v0 + tid];

    const int frow = tid >> 3, fkq = tid & 7;
    auto fill = [&](int ch, int b) {
        const int kb = ch * 64;
        const u32 buf = sbase + b * BUFSTR;
        const u32 swA = SWZ((u32)(frow * 128 + fkq * 16));
        cpa16(buf + AHI_OFF + swA, g_hhb[hp] + frow * HID + kb + fkq * 8);
        cpa16(buf + ALO_OFF + swA, g_hlb[hp] + frow * HID + kb + fkq * 8);
        #pragma unroll
        for (int i = 0; i < 4; i++) {
            int row = frow + i * 64;
            u32 sw = SWZ((u32)(row * 128 + fkq * 16));
            cpa16(buf + BHI_OFF + sw, g_whi + (size_t)(v0 + row) * HID + kb + fkq * 8);
            cpa16(buf + BLO_OFF + sw, g_wlo + (size_t)(v0 + row) * HID + kb + fkq * 8);
        }
        CPA_COMMIT();
    };

    float D0[2][4][4], D1[2][4][4];
    #pragma unroll
    for (int a = 0; a < 2; a++)
        #pragma unroll
        for (int b = 0; b < 4; b++)
            #pragma unroll
            for (int c = 0; c < 4; c++) { D0[a][b][c] = 0.f; D1[a][b][c] = 0.f; }

    const int aRow = (lane & 7) + ((lane & 8) ? 8 : 0);
    const int aCol = (lane & 16) ? 16 : 0;
    const int bRow = (lane & 7) + ((lane & 16) ? 8 : 0);
    const int bCol = (lane & 8) ? 16 : 0;

    fill(0, 0);
    CPA_WAIT0();
    __syncthreads();

    for (int ch = 0; ch < NCHUNK; ch++) {
        const int b = ch & 1;
        if (ch + 1 < NCHUNK) fill(ch + 1, b ^ 1);
        const u32 buf = sbase + b * BUFSTR;
        #pragma unroll
        for (int k16 = 0; k16 < 4; k16++) {
            const int kkb = k16 * 32;
            u32 ahi[2][4], alo[2][4];
            #pragma unroll
            for (int tm = 0; tm < 2; tm++) {
                u32 off = SWZ((u32)((32 * wm + 16 * tm + aRow) * 128 + kkb + aCol));
                ldm4(ahi[tm], buf + AHI_OFF + off);
                ldm4(alo[tm], buf + ALO_OFF + off);
            }
            #pragma unroll
            for (int g = 0; g < 2; g++) {
                u32 off = SWZ((u32)((32 * wn + 16 * g + bRow) * 128 + kkb + bCol));
                u32 bhi[4], blo[4];
                ldm4(bhi, buf + BHI_OFF + off);
                ldm4(blo, buf + BLO_OFF + off);
                #pragma unroll
                for (int tm = 0; tm < 2; tm++) {
                    #pragma unroll
                    for (int h = 0; h < 2; h++) {
                        int tn = 2 * g + h;
                        mma16816(D0[tm][tn], ahi[tm], &bhi[2 * h]);
                        mma16816(D1[tm][tn], ahi[tm], &blo[2 * h]);
                        mma16816(D1[tm][tn], alo[tm], &bhi[2 * h]);
                    }
                }
            }
        }
        if (ch + 1 < NCHUNK) { CPA_WAIT0(); __syncthreads(); }
    }

    const int q  = lane >> 2;
    const int c2 = (lane & 3) * 2;
    float mv[4] = {-3.4e38f, -3.4e38f, -3.4e38f, -3.4e38f};
    int   mi[4] = {0, 0, 0, 0};
    #pragma unroll
    for (int tm = 0; tm < 2; tm++) {
        int r0 = 32 * wm + 16 * tm + q;
        int r1 = r0 + 8;
        float* p0 = out + (size_t)r0 * TSTEPS * VOC + (size_t)t * VOC + v0;
        float* p1 = out + (size_t)r1 * TSTEPS * VOC + (size_t)t * VOC + v0;
        const int s0 = 2 * tm, s1 = 2 * tm + 1;
        #pragma unroll
        for (int tn = 0; tn < 4; tn++) {
            int c = 32 * wn + 8 * tn + c2;
            float b0 = biasF[c], b1 = biasF[c + 1];
            float v00 = D0[tm][tn][0] + D1[tm][tn][0] * INV256 + b0;
            float v01 = D0[tm][tn][1] + D1[tm][tn][1] * INV256 + b1;
            float v10 = D0[tm][tn][2] + D1[tm][tn][2] * INV256 + b0;
            float v11 = D0[tm][tn][3] + D1[tm][tn][3] * INV256 + b1;
            *(float2*)&p0[c] = make_float2(v00, v01);
            *(float2*)&p1[c] = make_float2(v10, v11);
            int gi = v0 + c;
            if (v00 > mv[s0]) { mv[s0] = v00; mi[s0] = gi; }
            if (v01 > mv[s0]) { mv[s0] = v01; mi[s0] = gi + 1; }
            if (v10 > mv[s1]) { mv[s1] = v10; mi[s1] = gi; }
            if (v11 > mv[s1]) { mv[s1] = v11; mi[s1] = gi + 1; }
        }
    }
    #pragma unroll
    for (int off = 1; off <= 2; off <<= 1) {
        #pragma unroll
        for (int s = 0; s < 4; s++) {
            float ov = __shfl_xor_sync(0xffffffffu, mv[s], off);
            int   oi = __shfl_xor_sync(0xffffffffu, mi[s], off);
            if (ov > mv[s] || (ov == mv[s] && oi < mi[s])) { mv[s] = ov; mi[s] = oi; }
        }
    }
    if ((lane & 3) == 0) {
        const int rows[4] = {32 * wm + q, 32 * wm + q + 8,
                             32 * wm + 16 + q, 32 * wm + 24 + q};
        #pragma unroll
        for (int s = 0; s < 4; s++) {
            spv[rows[s] * 8 + wn] = mv[s];
            spi[rows[s] * 8 + wn] = mi[s];
        }
    }
    __syncthreads();
    if (tid < 64) {
        float bv = spv[tid * 8]; int bi = spi[tid * 8];
        #pragma unroll
        for (int j = 1; j < 8; j++) {
            float v = spv[tid * 8 + j];
            int   i = spi[tid * 8 + j];
            if (v > bv || (v == bv && i < bi)) { bv = v; bi = i; }
        }
        g_pval[tid * NLBLK + blockIdx.x] = bv;
        g_pidx[tid * NLBLK + blockIdx.x] = bi;
    }
}

// ---------------- launch -----------------------------------------------------
extern "C" void kernel_launch(void* const* d_in, const int* in_sizes, int n_in,
                              void* d_out, int out_size) {
    const float* z   = (const float*)d_in[0];
    const float* emb = (const float*)d_in[1];
    const float* wih = (const float*)d_in[2];
    const float* whh = (const float*)d_in[3];
    const float* bih = (const float*)d_in[4];
    const float* bhh = (const float*)d_in[5];
    const float* fcw = (const float*)d_in[6];
    const float* fcb = (const float*)d_in[7];
    const float* lw  = (const float*)d_in[8];
    const float* lb  = (const float*)d_in[9];
    float* out = (float*)d_out;

    static int smem_set = 0;
    if (!smem_set) {
        cudaFuncSetAttribute(k_logits,   cudaFuncAttributeMaxDynamicSharedMemorySize, DSMEM);
        cudaFuncSetAttribute(k_gatelstm, cudaFuncAttributeMaxDynamicSharedMemorySize, GDSM);
        smem_set = 1;
    }

    k_init<<<256, 256>>>(z, lw, lb);
    k_prep<<<VOC * HID / 1024, 256>>>(fcw);
    k_prep_emb<<<VOC * EMBD / 1024, 256>>>(emb);
    k_prep_w<<<4096, 384>>>(wih, whh, bih, bhh);
    for (int t = 0; t < TSTEPS; t++) {
        k_gatelstm<<<128, 256, GDSM>>>(t);
        k_logits<<<NLBLK, 512, DSMEM>>>(fcb, out, t);
    }
}